// round 13
// baseline (speedup 1.0000x reference)
#include <cuda_runtime.h>
#include <cstdint>
#include <math.h>

#define NUM_BINS 16
#define BOUND 3.0f
#define MIN_BIN_WIDTH 0.001f
#define MIN_BIN_HEIGHT 0.001f
#define MIN_DERIVATIVE 0.001f
#define MIN_LAMBDA 0.025f
#define EPS_C 1e-6f

#define TPB 64
#define TILE 64
#define P 63
#define SPE 32                    // staged floats per element (w16 + h16)
#define ROWSTRIDE 33              // +1 pad: lane-k reads hit distinct banks
#define BUF_WORDS (TILE * ROWSTRIDE)   // 2112 words = 8448 B per buffer

#define CP_ASYNC4(saddr, gptr) \
    asm volatile("cp.async.ca.shared.global [%0], [%1], 4;\n" :: "r"(saddr), "l"(gptr))
#define CP_COMMIT() asm volatile("cp.async.commit_group;\n" ::)
#define CP_WAIT1()  asm volatile("cp.async.wait_group 1;\n" ::)
#define CP_WAIT0()  asm volatile("cp.async.wait_group 0;\n" ::)

__global__ __launch_bounds__(TPB, 13) void lrs_kernel(
    const float* __restrict__ inputs,
    const float* __restrict__ params,
    float* __restrict__ out,
    int n, int ntiles)
{
    __shared__ float sm[2][BUF_WORDS];   // 2 * 8448 B = 16896 B -> 13 CTAs/SM

    const int tid = threadIdx.x;
    const int G = gridDim.x;
    const uint32_t sm_u32 = (uint32_t)__cvta_generic_to_shared(&sm[0][0]);

    // stage w+h (floats 0..31) of each row of tile t into buffer b.
    // i = k*64+tid -> element e=i>>5, float f=i&31; smem word = e*33+f = i+(i>>5).
    // Per warp-op: lanes cover one contiguous 128B gmem segment (fully coalesced).
    auto stage = [&](int t, int b) {
        const int base = t * TILE;
        const uint32_t sbase = sm_u32 + (uint32_t)b * (BUF_WORDS * 4);
        const float* gsrc = params + (size_t)base * P;
        if (base + TILE <= n) {
            #pragma unroll
            for (int k = 0; k < SPE; k++) {
                int i = k * TPB + tid;
                int e = i >> 5;
                int f = i & 31;
                CP_ASYNC4(sbase + (uint32_t)(i + (i >> 5)) * 4,
                          gsrc + (size_t)e * P + f);
            }
        } else {
            int rem = n - base;
            for (int i = tid; i < rem * SPE; i += TPB) {
                int e = i >> 5, f = i & 31;
                CP_ASYNC4(sbase + (uint32_t)(i + (i >> 5)) * 4,
                          gsrc + (size_t)e * P + f);
            }
        }
    };

    int t0 = blockIdx.x;
    if (t0 < ntiles) stage(t0, 0);
    CP_COMMIT();

    int j = 0;
    for (int t = t0; t < ntiles; t += G, j++) {
        int tn = t + G;
        if (tn < ntiles) {
            stage(tn, (j + 1) & 1);   // next tile's loads in flight during compute
            CP_COMMIT();
            CP_WAIT1();               // tile t's group complete
        } else {
            CP_WAIT0();
        }
        __syncthreads();

        const int elem = t * TILE + tid;
        if (elem < n) {
            const float* mp = &sm[j & 1][tid * ROWSTRIDE];
            const float* grow = params + (size_t)elem * P;
            const float x = __ldg(inputs + elem);

            // ========== widths softmax (register-resident, no max-sub) ==========
            float ew[NUM_BINS];
            float s = 0.0f;
            #pragma unroll
            for (int k = 0; k < NUM_BINS; k++) { ew[k] = __expf(mp[k]); s += ew[k]; }
            const float wscale = (1.0f - MIN_BIN_WIDTH * NUM_BINS) * __fdividef(1.0f, s);

            int cnt = (x >= -BOUND + EPS_C) ? 1 : 0;
            float cwL = -BOUND, cwR = BOUND;
            bool haveR = false;
            {
                float cum = 0.0f;
                #pragma unroll
                for (int k = 0; k < NUM_BINS; k++) {
                    cum += fmaf(wscale, ew[k], MIN_BIN_WIDTH);
                    float knot = (k == NUM_BINS - 1) ? BOUND : fmaf(cum, 2.0f * BOUND, -BOUND);
                    if (x >= knot + EPS_C) { cnt++; cwL = knot; }
                    else if (!haveR)       { haveR = true; cwR = knot; }
                }
            }
            const int bin = min(max(cnt - 1, 0), NUM_BINS - 1);
            const float in_w = cwR - cwL;

            // ---- 3 scattered loads issued NOW; consumed after the heights chain ----
            float dLraw = 0.0f, dRraw = 0.0f;
            if (bin > 0)            dLraw = __ldg(grow + (2 * NUM_BINS - 1) + bin);
            if (bin < NUM_BINS - 1) dRraw = __ldg(grow + 2 * NUM_BINS + bin);
            const float lamraw = __ldg(grow + (3 * NUM_BINS - 1) + bin);

            // ========== heights softmax (long MUFU chain hides the loads) ==========
            float eh[NUM_BINS];
            float sh = 0.0f;
            #pragma unroll
            for (int k = 0; k < NUM_BINS; k++) { eh[k] = __expf(mp[NUM_BINS + k]); sh += eh[k]; }
            const float hscale = (1.0f - MIN_BIN_HEIGHT * NUM_BINS) * __fdividef(1.0f, sh);

            float chL = -BOUND, chR = BOUND;
            {
                float cum = 0.0f;
                #pragma unroll
                for (int k = 0; k < NUM_BINS; k++) {
                    cum += fmaf(hscale, eh[k], MIN_BIN_HEIGHT);
                    float knot = (k == NUM_BINS - 1) ? BOUND : fmaf(cum, 2.0f * BOUND, -BOUND);
                    if (k + 1 == bin) chL = knot;
                    if (k == bin)     chR = knot;
                }
            }
            const float in_h = chR - chL;

            // ========== derivatives (2 softplus) + lambda (1 sigmoid) ==========
            const float edge = 1.0f - MIN_DERIVATIVE;
            float dL, dR;
            if (bin > 0)
                dL = MIN_DERIVATIVE + fmaxf(dLraw, 0.0f) + __logf(1.0f + __expf(-fabsf(dLraw)));
            else dL = edge;
            if (bin < NUM_BINS - 1)
                dR = MIN_DERIVATIVE + fmaxf(dRraw, 0.0f) + __logf(1.0f + __expf(-fabsf(dRraw)));
            else dR = edge;

            const float sig = __fdividef(1.0f, 1.0f + __expf(-lamraw));
            const float lam = fmaf(1.0f - 2.0f * MIN_LAMBDA, sig, MIN_LAMBDA);

            // ========== spline evaluation ==========
            const float r_inw = __fdividef(1.0f, in_w);
            const float r_inh = __fdividef(1.0f, in_h);
            const float wb  = sqrtf(__fdividef(dL, dR));
            const float lwb = lam * wb;
            const float wc  = (lam * dL + (wb - lwb) * dR) * in_w * r_inh;
            const float ya  = chL;
            const float yb  = in_h + chL;
            const float l1  = 1.0f - lam;
            const float yc  = __fdividef(lwb * yb + l1 * ya, l1 + lwb);

            const float theta  = (x - cwL) * r_inw;
            const bool  ind    = theta <= lam;
            const float ltheta = lam - theta;
            const float wcyc   = wc * yc;
            const float wcyctheta = wcyc * theta;
            const float wbyb   = wb * yb;
            const float numerator   = ind ? (wcyctheta + ya * ltheta)
                                          : ((wcyc - wcyctheta) - wbyb * ltheta);
            const float wctheta = wc * theta;
            const float denominator = ind ? (wctheta + ltheta)
                                          : ((wc - wctheta) - wb * ltheta);
            const float rden   = __fdividef(1.0f, denominator);
            const float result = numerator * rden;

            const float dnum = wc * (ind ? (lam * (yc - ya)) : ((wb - lwb) * (yb - yc))) * r_inw;
            const float lad  = __logf(dnum * rden * rden);

            const bool outside = (x < -BOUND) || (x > BOUND);
            out[elem]     = outside ? x : result;
            out[n + elem] = outside ? 0.0f : lad;
        }
        __syncthreads();          // all reads of buf[j&1] done before it is restaged
    }
}

extern "C" void kernel_launch(void* const* d_in, const int* in_sizes, int n_in,
                              void* d_out, int out_size) {
    const float* inputs = (const float*)d_in[0];
    const float* params = (const float*)d_in[1];
    float* out = (float*)d_out;
    int n = in_sizes[0];
    int ntiles = (n + TILE - 1) / TILE;
    int grid = 152 * 13;              // persistent: 13 CTAs/SM (16.9 KB smem each)
    if (grid > ntiles) grid = ntiles;
    lrs_kernel<<<grid, TPB>>>(inputs, params, out, n, ntiles);
}

// round 16
// speedup vs baseline: 1.5824x; 1.5824x over previous
#include <cuda_runtime.h>
#include <cstdint>
#include <math.h>

#define NUM_BINS 16
#define BOUND 3.0f
#define MIN_BIN_WIDTH 0.001f
#define MIN_BIN_HEIGHT 0.001f
#define MIN_DERIVATIVE 0.001f
#define MIN_LAMBDA 0.025f
#define EPS_C 1e-6f

#define TPB 64                 // 2 warps per CTA, each warp fully independent
#define ST 32                  // subtile: 32 elements per warp-pipeline
#define P 63                   // odd -> stride-63 smem rows conflict-free
#define ST_FLOATS (ST * P)     // 2016 floats = 8064 B per buffer
#define ST_VECS (ST_FLOATS / 4)  // 504

#define CP_ASYNC16(saddr, gptr) \
    asm volatile("cp.async.cg.shared.global [%0], [%1], 16;\n" :: "r"(saddr), "l"(gptr))
#define CP_COMMIT() asm volatile("cp.async.commit_group;\n" ::)
#define CP_WAIT1()  asm volatile("cp.async.wait_group 1;\n" ::)
#define CP_WAIT0()  asm volatile("cp.async.wait_group 0;\n" ::)

__global__ __launch_bounds__(TPB) void lrs_kernel(
    const float* __restrict__ inputs,
    const float* __restrict__ params,
    float* __restrict__ out,
    int n, int nst)
{
    // [warp][buffer]: warp-private double buffers; 4 * 8064 = 32256 B -> 7 CTAs/SM
    __shared__ float sm[2][2][ST_FLOATS];

    const int lane = threadIdx.x & 31;
    const int w    = threadIdx.x >> 5;
    const int G2   = gridDim.x * 2;          // warp-pipeline count

    // stage subtile t into this warp's buffer b (contiguous 8064 B, 504 vec16)
    auto stage = [&](int t, int b) {
        const float4* gsrc = reinterpret_cast<const float4*>(params + (size_t)(t * ST) * P);
        uint32_t sbase = (uint32_t)__cvta_generic_to_shared(&sm[w][b][0]);
        #pragma unroll
        for (int i = 0; i < ST_VECS / 32; i++) {       // 15 iters
            int idx = i * 32 + lane;
            CP_ASYNC16(sbase + (uint32_t)idx * 16, gsrc + idx);
        }
        int idx = (ST_VECS / 32) * 32 + lane;          // tail: 24 vecs
        if (idx < ST_VECS) CP_ASYNC16(sbase + (uint32_t)idx * 16, gsrc + idx);
    };

    const int tw0 = blockIdx.x * 2 + w;      // this warp's first subtile
    bool primed = false;
    if (tw0 < nst && (tw0 + 1) * ST <= n) { stage(tw0, 0); primed = true; }
    CP_COMMIT();

    int j = 0;
    for (int t = tw0; t < nst; t += G2, j++) {
        const int b = j & 1;
        const int tn = t + G2;
        const bool curfull = primed || ((t + 1) * ST <= n);
        bool staged_next = false;
        if (tn < nst && (tn + 1) * ST <= n) {
            stage(tn, b ^ 1);                // next subtile's loads in flight
            CP_COMMIT();
            CP_WAIT1();                      // current subtile's group complete
            staged_next = true;
        } else {
            CP_WAIT0();
        }
        primed = staged_next;
        __syncwarp();                        // cross-lane smem visibility

        const int elem = t * ST + lane;
        if (elem < n) {
            const float* mp = &sm[w][b][lane * P];
            const float* grow = params + (size_t)elem * P;   // ragged fallback only
            const bool full = curfull;
            const float x = __ldg(inputs + elem);

            // ========== widths softmax (register-resident, no max-sub) ==========
            float ew[NUM_BINS];
            float s = 0.0f;
            #pragma unroll
            for (int k = 0; k < NUM_BINS; k++) {
                float wr = full ? mp[k] : __ldg(grow + k);
                ew[k] = __expf(wr); s += ew[k];
            }
            const float wscale = (1.0f - MIN_BIN_WIDTH * NUM_BINS) * __fdividef(1.0f, s);

            int cnt = (x >= -BOUND + EPS_C) ? 1 : 0;
            float cwL = -BOUND, cwR = BOUND;
            bool haveR = false;
            {
                float cum = 0.0f;
                #pragma unroll
                for (int k = 0; k < NUM_BINS; k++) {
                    cum += fmaf(wscale, ew[k], MIN_BIN_WIDTH);
                    float knot = (k == NUM_BINS - 1) ? BOUND : fmaf(cum, 2.0f * BOUND, -BOUND);
                    if (x >= knot + EPS_C) { cnt++; cwL = knot; }
                    else if (!haveR)       { haveR = true; cwR = knot; }
                }
            }
            const int bin = min(max(cnt - 1, 0), NUM_BINS - 1);
            const float in_w = cwR - cwL;

            // d/lam from staged smem (no global round trip)
            const float dLraw  = full ? mp[(2 * NUM_BINS - 1) + bin] : __ldg(grow + (2 * NUM_BINS - 1) + bin);
            const float dRraw  = full ? mp[2 * NUM_BINS + bin]       : __ldg(grow + 2 * NUM_BINS + bin);
            const float lamraw = full ? mp[(3 * NUM_BINS - 1) + bin] : __ldg(grow + (3 * NUM_BINS - 1) + bin);

            // ========== heights softmax ==========
            float eh[NUM_BINS];
            float sh = 0.0f;
            #pragma unroll
            for (int k = 0; k < NUM_BINS; k++) {
                float hr = full ? mp[NUM_BINS + k] : __ldg(grow + NUM_BINS + k);
                eh[k] = __expf(hr); sh += eh[k];
            }
            const float hscale = (1.0f - MIN_BIN_HEIGHT * NUM_BINS) * __fdividef(1.0f, sh);

            float chL = -BOUND, chR = BOUND;
            {
                float cum = 0.0f;
                #pragma unroll
                for (int k = 0; k < NUM_BINS; k++) {
                    cum += fmaf(hscale, eh[k], MIN_BIN_HEIGHT);
                    float knot = (k == NUM_BINS - 1) ? BOUND : fmaf(cum, 2.0f * BOUND, -BOUND);
                    if (k + 1 == bin) chL = knot;
                    if (k == bin)     chR = knot;
                }
            }
            const float in_h = chR - chL;

            // ========== derivatives (2 softplus) + lambda (1 sigmoid) ==========
            const float edge = 1.0f - MIN_DERIVATIVE;
            float dL, dR;
            if (bin > 0)
                dL = MIN_DERIVATIVE + fmaxf(dLraw, 0.0f) + __logf(1.0f + __expf(-fabsf(dLraw)));
            else dL = edge;
            if (bin < NUM_BINS - 1)
                dR = MIN_DERIVATIVE + fmaxf(dRraw, 0.0f) + __logf(1.0f + __expf(-fabsf(dRraw)));
            else dR = edge;

            const float sig = __fdividef(1.0f, 1.0f + __expf(-lamraw));
            const float lam = fmaf(1.0f - 2.0f * MIN_LAMBDA, sig, MIN_LAMBDA);

            // ========== spline evaluation ==========
            const float r_inw = __fdividef(1.0f, in_w);
            const float r_inh = __fdividef(1.0f, in_h);
            const float wb  = sqrtf(__fdividef(dL, dR));
            const float lwb = lam * wb;
            const float wc  = (lam * dL + (wb - lwb) * dR) * in_w * r_inh;
            const float ya  = chL;
            const float yb  = in_h + chL;
            const float l1  = 1.0f - lam;
            const float yc  = __fdividef(lwb * yb + l1 * ya, l1 + lwb);

            const float theta  = (x - cwL) * r_inw;
            const bool  ind    = theta <= lam;
            const float ltheta = lam - theta;
            const float wcyc   = wc * yc;
            const float wcyctheta = wcyc * theta;
            const float wbyb   = wb * yb;
            const float numerator   = ind ? (wcyctheta + ya * ltheta)
                                          : ((wcyc - wcyctheta) - wbyb * ltheta);
            const float wctheta = wc * theta;
            const float denominator = ind ? (wctheta + ltheta)
                                          : ((wc - wctheta) - wb * ltheta);
            const float rden   = __fdividef(1.0f, denominator);
            const float result = numerator * rden;

            const float dnum = wc * (ind ? (lam * (yc - ya)) : ((wb - lwb) * (yb - yc))) * r_inw;
            const float lad  = __logf(dnum * rden * rden);

            const bool outside = (x < -BOUND) || (x > BOUND);
            out[elem]     = outside ? x : result;
            out[n + elem] = outside ? 0.0f : lad;
        }
        __syncwarp();            // all lanes done reading buf b before it is restaged
    }
}

extern "C" void kernel_launch(void* const* d_in, const int* in_sizes, int n_in,
                              void* d_out, int out_size) {
    const float* inputs = (const float*)d_in[0];
    const float* params = (const float*)d_in[1];
    float* out = (float*)d_out;
    int n = in_sizes[0];
    int nst = (n + ST - 1) / ST;          // 32-element subtiles
    int grid = 152 * 7;                   // 7 CTAs/SM -> 14 warp-pipelines/SM
    if (grid * 2 > nst) grid = (nst + 1) / 2;
    lrs_kernel<<<grid, TPB>>>(inputs, params, out, n, nst);
}